// round 9
// baseline (speedup 1.0000x reference)
#include <cuda_runtime.h>

// Shared memory layout (float indices).
// SHC: double-buffered h, paired layout: addr(k,b) = buf*1024 + (k>>1)*16 + b*2 + (k&1)
//      k 0..63: h1 (layer0 output), k 64..127: h2 (layer1 output)
#define SHC    0        // 2048 floats (2 buffers x 1024)
#define SX     2048     // x tile [512][8]
#define SW1H2  6144     // Whh1 tid-indexed, u64 array [32 pairs][256 tid] = 16384 floats
#define SMEM_FLOATS 22528   // 90112 bytes

typedef unsigned long long u64;

__device__ __forceinline__ float ftanh(float v) {
    float y;
    asm("tanh.approx.f32 %0, %1;" : "=f"(y) : "f"(v));
    return y;
}
__device__ __forceinline__ float fsig(float v) {
    return fmaf(ftanh(0.5f * v), 0.5f, 0.5f);
}
__device__ __forceinline__ u64 packf2(float lo, float hi) {
    u64 r;
    asm("mov.b64 %0, {%1, %2};" : "=l"(r)
        : "r"(__float_as_uint(lo)), "r"(__float_as_uint(hi)));
    return r;
}
__device__ __forceinline__ float2 unpackf2(u64 v) {
    unsigned int lo, hi;
    asm("mov.b64 {%0, %1}, %2;" : "=r"(lo), "=r"(hi) : "l"(v));
    return make_float2(__uint_as_float(lo), __uint_as_float(hi));
}
// d(lo,hi) += a(lo,hi) * b(lo,hi)   — packed dual-FMA (Blackwell f32x2)
__device__ __forceinline__ void ffma2(u64& d, u64 a, u64 b) {
    asm("fma.rn.f32x2 %0, %1, %2, %0;" : "+l"(d) : "l"(a), "l"(b));
}

// 4x4 u64 transpose across the 4 lanes of a gate group (lane = ... | gg).
// In:  lane gg holds P[k] = (v[2k], v[2k+1]) for its gate row (row gg).
// Out: lane gg holds P[g'] = gate-g' values for batches (2gg, 2gg+1).
__device__ __forceinline__ void transpose4(u64 P[4], int gg) {
    u64 t0 = (gg & 1) ? P[0] : P[1];
    u64 t1 = (gg & 1) ? P[2] : P[3];
    t0 = __shfl_xor_sync(0xffffffffu, t0, 1);
    t1 = __shfl_xor_sync(0xffffffffu, t1, 1);
    if (gg & 1) { P[0] = t0; P[2] = t1; } else { P[1] = t0; P[3] = t1; }
    u64 u0 = (gg & 2) ? P[0] : P[2];
    u64 u1 = (gg & 2) ? P[1] : P[3];
    u0 = __shfl_xor_sync(0xffffffffu, u0, 2);
    u1 = __shfl_xor_sync(0xffffffffu, u1, 2);
    if (gg & 2) { P[0] = u0; P[1] = u1; } else { P[2] = u0; P[3] = u1; }
}

__global__ void __launch_bounds__(256, 1)
lstm2_kernel(const float* __restrict__ x,
             const float* __restrict__ Wih0, const float* __restrict__ Whh0,
             const float* __restrict__ bih0, const float* __restrict__ bhh0,
             const float* __restrict__ Wih1, const float* __restrict__ Whh1,
             const float* __restrict__ bih1, const float* __restrict__ bhh1,
             const float* __restrict__ Wfc,  const float* __restrict__ bfc,
             float* __restrict__ out)
{
    extern __shared__ float sm[];
    u64* smW = (u64*)&sm[SW1H2];
    const int tid = threadIdx.x;
    const int gg  = tid & 3;             // gate index (i,f,g,o) within the 4-lane group
    const int j   = tid >> 2;            // hidden unit owned by this group (0..63)
    const int r   = gg * 64 + j;         // gate row in torch [4H] layout
    const int b0  = blockIdx.x * 8;      // batch base for this CTA

    const float wx_g    = Wih0[r];                       // [4H, I=1]
    const float bias0_g = bih0[r] + bhh0[r];
    const u64   init1   = packf2(bih1[r] + bhh1[r], 0.f);

    // ---- Persistent weights in registers (k-pair packed) ----
    u64 w0p[32];   // Whh0 row r
    u64 w1p[32];   // Wih1 row r  (layer1 input half, multiplies h1)
    {
        const u64* p0 = (const u64*)(Whh0 + r * 64);
        const u64* pi = (const u64*)(Wih1 + r * 64);
        const u64* ph = (const u64*)(Whh1 + r * 64);
        #pragma unroll
        for (int q = 0; q < 32; ++q) w0p[q] = p0[q];
        #pragma unroll
        for (int q = 0; q < 32; ++q) w1p[q] = pi[q];
        // Whh1 (h2 half) -> smem, tid-indexed so gate-loop LDS.64 is conflict-free
        #pragma unroll
        for (int q = 0; q < 32; ++q) smW[q * 256 + tid] = ph[q];
    }

    // ---- x tile: [t][b] layout ----
    for (int idx = tid; idx < 4096; idx += 256) {
        int t = idx >> 3, b = idx & 7;
        sm[SX + idx] = x[(b0 + b) * 512 + t];
    }
    // ---- Zero both h buffers ----
    for (int idx = tid; idx < 2048; idx += 256) sm[SHC + idx] = 0.f;
    __syncthreads();

    // Cell states in registers: this lane owns unit j, batches 2gg, 2gg+1
    float c0a = 0.f, c0b = 0.f;   // layer 0
    float c1a = 0.f, c1b = 0.f;   // layer 1
    const int hoff1 = (j >> 1) * 16 + 4 * gg + (j & 1);          // h1 slot (batch 2gg)
    const int hoff2 = 512 + (j >> 1) * 16 + 4 * gg + (j & 1);    // h2 slot

    // Pipelined loop: iter s computes L0 gates for t=s and L1 gates for t=s-1,
    // sharing h1 broadcast loads. Reads h from buf[s&1], writes to buf[(s+1)&1].
    for (int s = 0; s <= 512; ++s) {
        const bool doL0 = (s < 512);
        const bool doL1 = (s > 0);
        const float* hbase = &sm[SHC + (s & 1) * 1024];
        float*       hdst  = &sm[SHC + ((s + 1) & 1) * 1024];

        // ===== Merged gate phase =====
        const float4* xr = (const float4*)&sm[SX + (s & 511) * 8];
        float4 xa = xr[0], xb = xr[1];
        u64 a0 = packf2(fmaf(wx_g, xa.x, bias0_g), 0.f);
        u64 a1 = packf2(fmaf(wx_g, xa.y, bias0_g), 0.f);
        u64 a2 = packf2(fmaf(wx_g, xa.z, bias0_g), 0.f);
        u64 a3 = packf2(fmaf(wx_g, xa.w, bias0_g), 0.f);
        u64 a4 = packf2(fmaf(wx_g, xb.x, bias0_g), 0.f);
        u64 a5 = packf2(fmaf(wx_g, xb.y, bias0_g), 0.f);
        u64 a6 = packf2(fmaf(wx_g, xb.z, bias0_g), 0.f);
        u64 a7 = packf2(fmaf(wx_g, xb.w, bias0_g), 0.f);
        u64 q0 = init1, q1 = init1, q2 = init1, q3 = init1;
        u64 q4 = init1, q5 = init1, q6 = init1, q7 = init1;

        // h1 pairs: each broadcast load feeds BOTH layers (1 LDS : 4 ffma2)
        #pragma unroll
        for (int p = 0; p < 32; ++p) {
            const ulonglong2* hp = (const ulonglong2*)&hbase[p * 16];
            u64 w0 = w0p[p], w1 = w1p[p];
            ulonglong2 h01 = hp[0];
            ffma2(a0, w0, h01.x); ffma2(q0, w1, h01.x);
            ffma2(a1, w0, h01.y); ffma2(q1, w1, h01.y);
            ulonglong2 h23 = hp[1];
            ffma2(a2, w0, h23.x); ffma2(q2, w1, h23.x);
            ffma2(a3, w0, h23.y); ffma2(q3, w1, h23.y);
            ulonglong2 h45 = hp[2];
            ffma2(a4, w0, h45.x); ffma2(q4, w1, h45.x);
            ffma2(a5, w0, h45.y); ffma2(q5, w1, h45.y);
            ulonglong2 h67 = hp[3];
            ffma2(a6, w0, h67.x); ffma2(q6, w1, h67.x);
            ffma2(a7, w0, h67.y); ffma2(q7, w1, h67.y);
        }
        // h2 pairs: layer1 recurrent half, weights from tid-indexed smem
        #pragma unroll
        for (int p = 0; p < 32; ++p) {
            const ulonglong2* hp = (const ulonglong2*)&hbase[512 + p * 16];
            u64 w1 = smW[p * 256 + tid];
            ulonglong2 h01 = hp[0];
            ffma2(q0, w1, h01.x); ffma2(q1, w1, h01.y);
            ulonglong2 h23 = hp[1];
            ffma2(q2, w1, h23.x); ffma2(q3, w1, h23.y);
            ulonglong2 h45 = hp[2];
            ffma2(q4, w1, h45.x); ffma2(q5, w1, h45.y);
            ulonglong2 h67 = hp[3];
            ffma2(q6, w1, h67.x); ffma2(q7, w1, h67.y);
        }

        // ===== Layer 0 update (registers + shuffles, no smem gates, no barrier) =====
        if (doL0) {
            float2 p0 = unpackf2(a0), p1 = unpackf2(a1), p2 = unpackf2(a2), p3 = unpackf2(a3);
            float2 p4 = unpackf2(a4), p5 = unpackf2(a5), p6 = unpackf2(a6), p7 = unpackf2(a7);
            u64 P[4];
            P[0] = packf2(p0.x + p0.y, p1.x + p1.y);
            P[1] = packf2(p2.x + p2.y, p3.x + p3.y);
            P[2] = packf2(p4.x + p4.y, p5.x + p5.y);
            P[3] = packf2(p6.x + p6.y, p7.x + p7.y);
            transpose4(P, gg);   // -> P[0]=i, P[1]=f, P[2]=g, P[3]=o for batches 2gg,2gg+1
            float2 iv = unpackf2(P[0]), fv = unpackf2(P[1]);
            float2 gv = unpackf2(P[2]), ov = unpackf2(P[3]);
            c0a = fsig(fv.x) * c0a + fsig(iv.x) * ftanh(gv.x);
            c0b = fsig(fv.y) * c0b + fsig(iv.y) * ftanh(gv.y);
            hdst[hoff1]     = fsig(ov.x) * ftanh(c0a);
            hdst[hoff1 + 2] = fsig(ov.y) * ftanh(c0b);
        }
        // ===== Layer 1 update =====
        if (doL1) {
            float2 p0 = unpackf2(q0), p1 = unpackf2(q1), p2 = unpackf2(q2), p3 = unpackf2(q3);
            float2 p4 = unpackf2(q4), p5 = unpackf2(q5), p6 = unpackf2(q6), p7 = unpackf2(q7);
            u64 P[4];
            P[0] = packf2(p0.x + p0.y, p1.x + p1.y);
            P[1] = packf2(p2.x + p2.y, p3.x + p3.y);
            P[2] = packf2(p4.x + p4.y, p5.x + p5.y);
            P[3] = packf2(p6.x + p6.y, p7.x + p7.y);
            transpose4(P, gg);
            float2 iv = unpackf2(P[0]), fv = unpackf2(P[1]);
            float2 gv = unpackf2(P[2]), ov = unpackf2(P[3]);
            c1a = fsig(fv.x) * c1a + fsig(iv.x) * ftanh(gv.x);
            c1b = fsig(fv.y) * c1b + fsig(iv.y) * ftanh(gv.y);
            hdst[hoff2]     = fsig(ov.x) * ftanh(c1a);
            hdst[hoff2 + 2] = fsig(ov.y) * ftanh(c1b);
        }
        __syncthreads();   // h writes (buf (s+1)&1) -> next-iter reads
    }

    // ===== Final FC on h2[T-1]: O=1 =====
    // Last h2 write was iter s=512 into buf[(512+1)&1] = buf 1.
    if (tid < 8) {
        float acc = bfc[0];
        #pragma unroll 8
        for (int k = 64; k < 128; ++k)
            acc = fmaf(Wfc[k - 64],
                       sm[SHC + 1024 + (k >> 1) * 16 + tid * 2 + (k & 1)], acc);
        out[b0 + tid] = acc;
    }
}

extern "C" void kernel_launch(void* const* d_in, const int* in_sizes, int n_in,
                              void* d_out, int out_size)
{
    const float* x    = (const float*)d_in[0];
    const float* Wih0 = (const float*)d_in[1];
    const float* Whh0 = (const float*)d_in[2];
    const float* bih0 = (const float*)d_in[3];
    const float* bhh0 = (const float*)d_in[4];
    const float* Wih1 = (const float*)d_in[5];
    const float* Whh1 = (const float*)d_in[6];
    const float* bih1 = (const float*)d_in[7];
    const float* bhh1 = (const float*)d_in[8];
    const float* Wfc  = (const float*)d_in[9];
    const float* bfc  = (const float*)d_in[10];
    float* out = (float*)d_out;

    cudaFuncSetAttribute(lstm2_kernel,
                         cudaFuncAttributeMaxDynamicSharedMemorySize,
                         SMEM_FLOATS * sizeof(float));
    lstm2_kernel<<<128, 256, SMEM_FLOATS * sizeof(float)>>>(
        x, Wih0, Whh0, bih0, bhh0, Wih1, Whh1, bih1, bhh1, Wfc, bfc, out);
}

// round 14
// speedup vs baseline: 1.6586x; 1.6586x over previous
#include <cuda_runtime.h>

// Shared memory layout (float indices).
// SHC paired layout: addr(k,b) = (k>>1)*16 + b*2 + (k&1); k 0..63: h1, 64..127: h2
#define SHC   0        // 1024 floats
#define SC0   1024     // c0 [64][8]
#define SC1   1536     // c1 [64][8]
#define SGT0  2048     // layer0 gates [256][8]
#define SGT1  4096     // layer1 gates [256][8]
#define SX    6144     // x tile [512][8]
#define SW    10240    // Whh1 tid-indexed: u64 [32 pairs][256 tid] = 16384 floats
#define SMEM_FLOATS 26624   // 106496 bytes

typedef unsigned long long u64;

__device__ __forceinline__ float ftanh(float v) {
    float y;
    asm("tanh.approx.f32 %0, %1;" : "=f"(y) : "f"(v));
    return y;
}
__device__ __forceinline__ float fsig(float v) {
    return fmaf(ftanh(0.5f * v), 0.5f, 0.5f);
}
__device__ __forceinline__ u64 packf2(float lo, float hi) {
    u64 r;
    asm("mov.b64 %0, {%1, %2};" : "=l"(r)
        : "r"(__float_as_uint(lo)), "r"(__float_as_uint(hi)));
    return r;
}
__device__ __forceinline__ float2 unpackf2(u64 v) {
    unsigned int lo, hi;
    asm("mov.b64 {%0, %1}, %2;" : "=r"(lo), "=r"(hi) : "l"(v));
    return make_float2(__uint_as_float(lo), __uint_as_float(hi));
}
// d(lo,hi) += a(lo,hi) * b(lo,hi)   — packed dual-FMA (Blackwell f32x2)
__device__ __forceinline__ void ffma2(u64& d, u64 a, u64 b) {
    asm("fma.rn.f32x2 %0, %1, %2, %0;" : "+l"(d) : "l"(a), "l"(b));
}

__global__ void __launch_bounds__(256, 1)
lstm2_kernel(const float* __restrict__ x,
             const float* __restrict__ Wih0, const float* __restrict__ Whh0,
             const float* __restrict__ bih0, const float* __restrict__ bhh0,
             const float* __restrict__ Wih1, const float* __restrict__ Whh1,
             const float* __restrict__ bih1, const float* __restrict__ bhh1,
             const float* __restrict__ Wfc,  const float* __restrict__ bfc,
             float* __restrict__ out)
{
    extern __shared__ float sm[];
    u64* smW = (u64*)&sm[SW];
    const int tid = threadIdx.x;
    const int g   = tid;                 // gate row owned by this thread (0..255)
    const int b0  = blockIdx.x * 8;      // batch base for this CTA

    const float wx_g    = Wih0[g];                       // [4H, I=1]
    const float bias0_g = bih0[g] + bhh0[g];
    const u64   init1   = packf2(bih1[g] + bhh1[g], 0.f);

    // ---- Weights: Whh0 + Wih1 rows in registers; Whh1 row in smem (tid-indexed) ----
    u64 w0p[32];   // Whh0 row g         (multiplies h1_{t-1} for layer0)
    u64 w1p[32];   // Wih1 row g         (multiplies h1_t     for layer1)
    {
        const u64* p0 = (const u64*)(Whh0 + g * 64);
        const u64* pi = (const u64*)(Wih1 + g * 64);
        const u64* ph = (const u64*)(Whh1 + g * 64);
        #pragma unroll
        for (int q = 0; q < 32; ++q) w0p[q] = p0[q];
        #pragma unroll
        for (int q = 0; q < 32; ++q) w1p[q] = pi[q];
        #pragma unroll
        for (int q = 0; q < 32; ++q) smW[q * 256 + tid] = ph[q];   // conflict-free LDS.64 later
    }

    // ---- x tile: [t][b] layout ----
    for (int idx = tid; idx < 4096; idx += 256) {
        int t = idx >> 3, b = idx & 7;
        sm[SX + idx] = x[(b0 + b) * 512 + t];
    }
    // ---- Zero state ----
    for (int idx = tid; idx < 1024; idx += 256) sm[SHC + idx] = 0.f;
    for (int idx = tid; idx < 512;  idx += 256) { sm[SC0 + idx] = 0.f; sm[SC1 + idx] = 0.f; }
    __syncthreads();

    const int bb = tid & 7;        // batch lane for update phase
    const int j0 = tid >> 3;       // hidden-unit base (0..31), +32 for second task

    // Pipelined loop: iter s computes L0 gates for t=s (reads h1_{s-1}) and
    // L1 gates for t=s-1 (reads h1_{s-1}, h2_{s-2}) in ONE merged pass that
    // shares the h1 broadcast loads. Epilogue s=512 runs L1 only.
    for (int s = 0; s <= 512; ++s) {
        const bool doL0 = (s < 512);
        const bool doL1 = (s > 0);
        // ===== Merged gate phase =====
        {
            const float4* xr = (const float4*)&sm[SX + (s & 511) * 8];
            float4 xa = xr[0], xb = xr[1];
            u64 a0 = packf2(fmaf(wx_g, xa.x, bias0_g), 0.f);
            u64 a1 = packf2(fmaf(wx_g, xa.y, bias0_g), 0.f);
            u64 a2 = packf2(fmaf(wx_g, xa.z, bias0_g), 0.f);
            u64 a3 = packf2(fmaf(wx_g, xa.w, bias0_g), 0.f);
            u64 a4 = packf2(fmaf(wx_g, xb.x, bias0_g), 0.f);
            u64 a5 = packf2(fmaf(wx_g, xb.y, bias0_g), 0.f);
            u64 a6 = packf2(fmaf(wx_g, xb.z, bias0_g), 0.f);
            u64 a7 = packf2(fmaf(wx_g, xb.w, bias0_g), 0.f);
            u64 q0 = init1, q1 = init1, q2 = init1, q3 = init1;
            u64 q4 = init1, q5 = init1, q6 = init1, q7 = init1;

            // h1 pairs: each broadcast load feeds BOTH layers (1 LDS : 4 ffma2)
            #pragma unroll
            for (int j = 0; j < 32; ++j) {
                const ulonglong2* hp = (const ulonglong2*)&sm[SHC + j * 16];
                u64 w0 = w0p[j], w1 = w1p[j];
                ulonglong2 h01 = hp[0];
                ffma2(a0, w0, h01.x); ffma2(q0, w1, h01.x);
                ffma2(a1, w0, h01.y); ffma2(q1, w1, h01.y);
                ulonglong2 h23 = hp[1];
                ffma2(a2, w0, h23.x); ffma2(q2, w1, h23.x);
                ffma2(a3, w0, h23.y); ffma2(q3, w1, h23.y);
                ulonglong2 h45 = hp[2];
                ffma2(a4, w0, h45.x); ffma2(q4, w1, h45.x);
                ffma2(a5, w0, h45.y); ffma2(q5, w1, h45.y);
                ulonglong2 h67 = hp[3];
                ffma2(a6, w0, h67.x); ffma2(q6, w1, h67.x);
                ffma2(a7, w0, h67.y); ffma2(q7, w1, h67.y);
            }
            // h2 pairs: layer1 recurrent half; weights from tid-indexed smem
            #pragma unroll
            for (int j = 0; j < 32; ++j) {
                const ulonglong2* hp = (const ulonglong2*)&sm[SHC + 512 + j * 16];
                u64 w1 = smW[j * 256 + tid];
                ulonglong2 h01 = hp[0];
                ffma2(q0, w1, h01.x); ffma2(q1, w1, h01.y);
                ulonglong2 h23 = hp[1];
                ffma2(q2, w1, h23.x); ffma2(q3, w1, h23.y);
                ulonglong2 h45 = hp[2];
                ffma2(q4, w1, h45.x); ffma2(q5, w1, h45.y);
                ulonglong2 h67 = hp[3];
                ffma2(q6, w1, h67.x); ffma2(q7, w1, h67.y);
            }
            if (doL0) {
                float2 p0 = unpackf2(a0), p1 = unpackf2(a1), p2 = unpackf2(a2), p3 = unpackf2(a3);
                float2 p4 = unpackf2(a4), p5 = unpackf2(a5), p6 = unpackf2(a6), p7 = unpackf2(a7);
                float4* gp = (float4*)&sm[SGT0 + g * 8];
                gp[0] = make_float4(p0.x + p0.y, p1.x + p1.y, p2.x + p2.y, p3.x + p3.y);
                gp[1] = make_float4(p4.x + p4.y, p5.x + p5.y, p6.x + p6.y, p7.x + p7.y);
            }
            if (doL1) {
                float2 p0 = unpackf2(q0), p1 = unpackf2(q1), p2 = unpackf2(q2), p3 = unpackf2(q3);
                float2 p4 = unpackf2(q4), p5 = unpackf2(q5), p6 = unpackf2(q6), p7 = unpackf2(q7);
                float4* gp = (float4*)&sm[SGT1 + g * 8];
                gp[0] = make_float4(p0.x + p0.y, p1.x + p1.y, p2.x + p2.y, p3.x + p3.y);
                gp[1] = make_float4(p4.x + p4.y, p5.x + p5.y, p6.x + p6.y, p7.x + p7.y);
            }
        }
        __syncthreads();
        // ===== Merged state update =====
        if (doL0) {
            #pragma unroll
            for (int u = 0; u < 2; ++u) {
                int j = j0 + 32 * u;
                float iv = sm[SGT0 + (j)       * 8 + bb];
                float fv = sm[SGT0 + (64 + j)  * 8 + bb];
                float gv = sm[SGT0 + (128 + j) * 8 + bb];
                float ov = sm[SGT0 + (192 + j) * 8 + bb];
                float c  = sm[SC0 + j * 8 + bb];
                float cn = fsig(fv) * c + fsig(iv) * ftanh(gv);
                sm[SC0 + j * 8 + bb] = cn;
                sm[SHC + (j >> 1) * 16 + bb * 2 + (j & 1)] = fsig(ov) * ftanh(cn);  // h1_s
            }
        }
        if (doL1) {
            #pragma unroll
            for (int u = 0; u < 2; ++u) {
                int j = j0 + 32 * u;
                float iv = sm[SGT1 + (j)       * 8 + bb];
                float fv = sm[SGT1 + (64 + j)  * 8 + bb];
                float gv = sm[SGT1 + (128 + j) * 8 + bb];
                float ov = sm[SGT1 + (192 + j) * 8 + bb];
                float c  = sm[SC1 + j * 8 + bb];
                float cn = fsig(fv) * c + fsig(iv) * ftanh(gv);
                sm[SC1 + j * 8 + bb] = cn;
                sm[SHC + (32 + (j >> 1)) * 16 + bb * 2 + (j & 1)] = fsig(ov) * ftanh(cn); // h2_{s-1}
            }
        }
        __syncthreads();
    }

    // ===== Final FC on h2[T-1]: O=1 =====
    if (tid < 8) {
        float acc = bfc[0];
        #pragma unroll 8
        for (int j = 0; j < 64; ++j) {
            int k = 64 + j;
            acc = fmaf(Wfc[j], sm[SHC + (k >> 1) * 16 + tid * 2 + (k & 1)], acc);
        }
        out[b0 + tid] = acc;
    }
}

extern "C" void kernel_launch(void* const* d_in, const int* in_sizes, int n_in,
                              void* d_out, int out_size)
{
    const float* x    = (const float*)d_in[0];
    const float* Wih0 = (const float*)d_in[1];
    const float* Whh0 = (const float*)d_in[2];
    const float* bih0 = (const float*)d_in[3];
    const float* bhh0 = (const float*)d_in[4];
    const float* Wih1 = (const float*)d_in[5];
    const float* Whh1 = (const float*)d_in[6];
    const float* bih1 = (const float*)d_in[7];
    const float* bhh1 = (const float*)d_in[8];
    const float* Wfc  = (const float*)d_in[9];
    const float* bfc  = (const float*)d_in[10];
    float* out = (float*)d_out;

    cudaFuncSetAttribute(lstm2_kernel,
                         cudaFuncAttributeMaxDynamicSharedMemorySize,
                         SMEM_FLOATS * sizeof(float));
    lstm2_kernel<<<128, 256, SMEM_FLOATS * sizeof(float)>>>(
        x, Wih0, Whh0, bih0, bhh0, Wih1, Whh1, bih1, bhh1, Wfc, bfc, out);
}